// round 1
// baseline (speedup 1.0000x reference)
#include <cuda_runtime.h>
#include <math.h>
#include <float.h>

// Problem dims
#define B_   2
#define N_   2048
#define D_   1024
#define H_   16
#define DH_  64
#define C_   64
#define NK_  2049            // N+1 (null kv prepended)
#define BH_  (B_*H_)         // 32
#define ROWS_ (B_*N_)        // 4096
#define LDBIAS_ (C_+N_)      // 2112

// Scratch (device globals: allocation-free rule)
__device__ float g_xn[ROWS_*D_];        // layernormed x
__device__ float g_q [BH_*N_ *DH_];     // head-major q
__device__ float g_k [BH_*NK_*DH_];     // head-major k (row 0 = null)
__device__ float g_v [BH_*NK_*DH_];     // head-major v (row 0 = null)
__device__ float g_ao[ROWS_*D_];        // attention output (b,n,h*64+d)
__device__ int   g_mask_mode;           // 1 = 1-byte mask, 0 = 4-byte mask

// ---------------------------------------------------------------------------
// Mask dtype detection: bool may arrive as int8/bool (1B) or int32/float32 (4B).
// For 4-byte 0/1 layouts (int 1 = [01 00 00 00], float 1.0 = [00 00 80 3F]),
// byte offsets == 1 (mod 4) are ALWAYS zero. For a random 1-byte 0/1 mask they
// are nonzero ~half the time. Reads limited to first 4096 bytes (safe in all
// layouts since element count is 4096).
// ---------------------------------------------------------------------------
__global__ void detect_mask_kernel(const unsigned char* __restrict__ cm) {
    __shared__ int flag;
    if (threadIdx.x == 0) flag = 0;
    __syncthreads();
    int any = 0;
    for (int i = threadIdx.x; i < 1024; i += blockDim.x)
        if (cm[4*i + 1] != 0) any = 1;
    if (any) atomicOr(&flag, 1);
    __syncthreads();
    if (threadIdx.x == 0) g_mask_mode = flag;
}

// ---------------------------------------------------------------------------
// LayerNorm: one block per row (4096 rows x 1024), 256 threads, float4 per thread
// ---------------------------------------------------------------------------
__global__ void ln_kernel(const float* __restrict__ x,
                          const float* __restrict__ gamma) {
    const int row = blockIdx.x;
    const int tid = threadIdx.x;
    const float4 a = ((const float4*)(x + (size_t)row * D_))[tid];
    float s  = a.x + a.y + a.z + a.w;
    float s2 = a.x*a.x + a.y*a.y + a.z*a.z + a.w*a.w;
    #pragma unroll
    for (int o = 16; o > 0; o >>= 1) {
        s  += __shfl_xor_sync(0xFFFFFFFFu, s,  o);
        s2 += __shfl_xor_sync(0xFFFFFFFFu, s2, o);
    }
    __shared__ float rs[8], rs2[8];
    if ((tid & 31) == 0) { rs[tid >> 5] = s; rs2[tid >> 5] = s2; }
    __syncthreads();
    float S = 0.f, S2 = 0.f;
    #pragma unroll
    for (int i = 0; i < 8; i++) { S += rs[i]; S2 += rs2[i]; }
    const float mu  = S * (1.0f / D_);
    const float var = S2 * (1.0f / D_) - mu * mu;
    const float inv = rsqrtf(var + 1e-5f);
    const float4 g = ((const float4*)gamma)[tid];
    float4 o;
    o.x = (a.x - mu) * inv * g.x;
    o.y = (a.y - mu) * inv * g.y;
    o.z = (a.z - mu) * inv * g.z;
    o.w = (a.w - mu) * inv * g.w;
    ((float4*)(g_xn + (size_t)row * D_))[tid] = o;
}

// ---------------------------------------------------------------------------
// QKV GEMM: C(4096 x 3072) = xn @ [Wq | Wkv], tiled 128x128x8, 256 threads,
// each thread computes 8x8. Epilogue scatters into head-major q/k/v
// (k/v shifted by +1 row to leave slot 0 for the null kv).
// ---------------------------------------------------------------------------
__global__ void gemm_qkv_kernel(const float* __restrict__ Wq,
                                const float* __restrict__ Wkv) {
    const int bm = blockIdx.y * 128;
    const int bn = blockIdx.x * 128;
    __shared__ float As[8][128];
    __shared__ float Bs[8][128];
    const float* __restrict__ A = g_xn;
    const float* __restrict__ Bp;
    int ldb, cb;
    if (bn < 1024) { Bp = Wq;  ldb = 1024; cb = bn; }
    else           { Bp = Wkv; ldb = 2048; cb = bn - 1024; }

    const int tid  = threadIdx.x;
    const int arow = tid >> 1, ak = (tid & 1) * 4;
    const int bkr  = tid >> 5, bcol = (tid & 31) * 4;
    const int ty   = tid >> 4, tx = tid & 15;

    float acc[8][8] = {};
    for (int k0 = 0; k0 < 1024; k0 += 8) {
        float4 a4 = *(const float4*)(A + (size_t)(bm + arow) * 1024 + k0 + ak);
        As[ak+0][arow] = a4.x; As[ak+1][arow] = a4.y;
        As[ak+2][arow] = a4.z; As[ak+3][arow] = a4.w;
        *(float4*)&Bs[bkr][bcol] = *(const float4*)(Bp + (size_t)(k0 + bkr) * ldb + cb + bcol);
        __syncthreads();
        #pragma unroll
        for (int kk = 0; kk < 8; kk++) {
            float ar[8], br[8];
            *(float4*)(ar)   = *(float4*)&As[kk][ty*8];
            *(float4*)(ar+4) = *(float4*)&As[kk][ty*8+4];
            *(float4*)(br)   = *(float4*)&Bs[kk][tx*8];
            *(float4*)(br+4) = *(float4*)&Bs[kk][tx*8+4];
            #pragma unroll
            for (int i = 0; i < 8; i++)
                #pragma unroll
                for (int j = 0; j < 8; j++)
                    acc[i][j] += ar[i] * br[j];
        }
        __syncthreads();
    }
    // Scatter epilogue (block is uniformly in q / k / v range)
    #pragma unroll
    for (int i = 0; i < 8; i++) {
        const int row = bm + ty*8 + i;
        const int b = row >> 11, n = row & 2047;
        #pragma unroll
        for (int j = 0; j < 8; j++) {
            const int col = bn + tx*8 + j;
            const float vv = acc[i][j];
            if (col < 1024) {
                const int h = col >> 6, d = col & 63;
                g_q[(((size_t)(b*H_ + h)) * N_ + n) * DH_ + d] = vv;
            } else if (col < 2048) {
                const int cc = col - 1024, h = cc >> 6, d = cc & 63;
                g_k[(((size_t)(b*H_ + h)) * NK_ + (n+1)) * DH_ + d] = vv;
            } else {
                const int cc = col - 2048, h = cc >> 6, d = cc & 63;
                g_v[(((size_t)(b*H_ + h)) * NK_ + (n+1)) * DH_ + d] = vv;
            }
        }
    }
}

// ---------------------------------------------------------------------------
// l2norm + scales + null kv fill. One warp per (bh, j) row, j in [0, 2049).
// j==0: normalize null_k -> g_k row 0, copy null_v. j>=1: normalize k row j
// (in place) and q row j-1 (in place).
// ---------------------------------------------------------------------------
__global__ void norm_kernel(const float* __restrict__ null_kv,
                            const float* __restrict__ q_scale,
                            const float* __restrict__ k_scale) {
    const int gw   = (blockIdx.x * blockDim.x + threadIdx.x) >> 5;
    const int lane = threadIdx.x & 31;
    if (gw >= BH_ * NK_) return;
    const int bh = gw / NK_, j = gw - bh * NK_;
    const int h  = bh & 15;
    const int d0 = lane, d1 = lane + 32;
    const float ks0 = k_scale[d0], ks1 = k_scale[d1];

    if (j == 0) {
        const float k0 = null_kv[h*DH_ + d0], k1 = null_kv[h*DH_ + d1];
        const float v0 = null_kv[H_*DH_ + h*DH_ + d0];
        const float v1 = null_kv[H_*DH_ + h*DH_ + d1];
        float ss = k0*k0 + k1*k1;
        #pragma unroll
        for (int o = 16; o > 0; o >>= 1) ss += __shfl_xor_sync(0xFFFFFFFFu, ss, o);
        const float inv = 1.0f / fmaxf(sqrtf(ss), 1e-12f);
        float* kp = g_k + (size_t)bh * NK_ * DH_;
        float* vp = g_v + (size_t)bh * NK_ * DH_;
        kp[d0] = k0*inv*ks0; kp[d1] = k1*inv*ks1;
        vp[d0] = v0;         vp[d1] = v1;
    } else {
        float* kp = g_k + ((size_t)bh * NK_ + j) * DH_;
        float* qp = g_q + ((size_t)bh * N_ + (j-1)) * DH_;
        const float k0 = kp[d0], k1 = kp[d1];
        const float q0 = qp[d0], q1 = qp[d1];
        float ssk = k0*k0 + k1*k1;
        float ssq = q0*q0 + q1*q1;
        #pragma unroll
        for (int o = 16; o > 0; o >>= 1) {
            ssk += __shfl_xor_sync(0xFFFFFFFFu, ssk, o);
            ssq += __shfl_xor_sync(0xFFFFFFFFu, ssq, o);
        }
        const float invk = 1.0f / fmaxf(sqrtf(ssk), 1e-12f);
        const float invq = 1.0f / fmaxf(sqrtf(ssq), 1e-12f);
        const float qs0 = q_scale[d0], qs1 = q_scale[d1];
        kp[d0] = k0*invk*ks0; kp[d1] = k1*invk*ks1;
        qp[d0] = q0*invq*qs0; qp[d1] = q1*invq*qs1;
    }
}

// ---------------------------------------------------------------------------
// Flash attention: grid = BH*32 blocks, 256 threads, 64 q-rows per block,
// streaming k/v tiles of 64 (33 tiles covering 2049 incl. null column).
// Online softmax with bias + mask fused. Dynamic smem ~64.3 KB.
// ---------------------------------------------------------------------------
__global__ void attn_kernel(const float* __restrict__ attn_bias,
                            const void*  __restrict__ cmask) {
    extern __shared__ float sm[];
    float* qs  = sm;               // 64x64
    float* ks  = sm + 4096;        // 64x64
    float* vs  = sm + 8192;        // 64x64
    float* ss  = sm + 12288;       // 64x64
    float* fac = sm + 16384;       // 64

    const int tid = threadIdx.x;
    const int qt  = blockIdx.x & 31;
    const int bh  = blockIdx.x >> 5;
    const int b   = bh >> 4;
    const int h   = bh & 15;
    const int i0  = qt * 64;
    const int mode = g_mask_mode;
    const unsigned char* m8  = (const unsigned char*)cmask;
    const unsigned int*  m32 = (const unsigned int*)cmask;

    // load q tile (contiguous)
    const float* qbase = g_q + ((size_t)bh * N_ + i0) * DH_;
    #pragma unroll
    for (int u = 0; u < 4; u++) {
        const int off = tid*4 + u*1024;
        *(float4*)(qs + off) = *(const float4*)(qbase + off);
    }

    float m_i = -FLT_MAX, l_i = 0.f;   // valid in threads tid<64
    float oacc[4][4] = {};
    const int ty = tid >> 4, tx = tid & 15;

    const float* kbase = g_k + (size_t)bh * NK_ * DH_;
    const float* vbase = g_v + (size_t)bh * NK_ * DH_;

    for (int t = 0; t < 33; t++) {
        const int jb = t * 64;
        const int navail = NK_ - jb;           // rows available in this tile
        // load k & v tiles (zero-fill tail)
        #pragma unroll
        for (int u = 0; u < 4; u++) {
            const int off = tid*4 + u*1024;
            float4 kk, vv;
            if ((off >> 6) < navail) {
                kk = *(const float4*)(kbase + (size_t)jb * DH_ + off);
                vv = *(const float4*)(vbase + (size_t)jb * DH_ + off);
            } else {
                kk = make_float4(0.f,0.f,0.f,0.f); vv = kk;
            }
            *(float4*)(ks + off) = kk;
            *(float4*)(vs + off) = vv;
        }
        __syncthreads();

        // S = q @ k^T  (each thread: 4x4)
        float sacc[4][4] = {};
        #pragma unroll
        for (int dc = 0; dc < 16; dc++) {
            const int d = dc * 4;
            float4 qv[4], kv[4];
            #pragma unroll
            for (int r = 0; r < 4; r++) qv[r] = *(float4*)(qs + (ty*4+r)*64 + d);
            #pragma unroll
            for (int c = 0; c < 4; c++) kv[c] = *(float4*)(ks + (tx*4+c)*64 + d);
            #pragma unroll
            for (int r = 0; r < 4; r++)
                #pragma unroll
                for (int c = 0; c < 4; c++)
                    sacc[r][c] += qv[r].x*kv[c].x + qv[r].y*kv[c].y
                                + qv[r].z*kv[c].z + qv[r].w*kv[c].w;
        }
        // bias + mask, write scores
        #pragma unroll
        for (int r = 0; r < 4; r++) {
            const int ig = i0 + ty*4 + r;
            const float* brow = attn_bias + (size_t)(C_ + ig) * LDBIAS_ + (C_ - 1);
            #pragma unroll
            for (int c = 0; c < 4; c++) {
                const int jg = jb + tx*4 + c;
                float sv;
                if (jg >= NK_)      sv = -FLT_MAX;
                else if (jg == 0)   sv = sacc[r][c] * 8.0f;
                else {
                    const bool mk = mode ? (m8[b*N_ + jg - 1] != 0)
                                         : (m32[b*N_ + jg - 1] != 0u);
                    sv = mk ? (sacc[r][c] * 8.0f + brow[jg]) : -FLT_MAX;
                }
                ss[(ty*4+r)*64 + tx*4 + c] = sv;
            }
        }
        __syncthreads();

        // online softmax (row owners = tid<64)
        if (tid < 64) {
            float* prow = ss + tid*64;
            float mloc = -FLT_MAX;
            #pragma unroll 8
            for (int j = 0; j < 64; j++) mloc = fmaxf(mloc, prow[j]);
            const float mnew = fmaxf(m_i, mloc);
            const float f = __expf(m_i - mnew);
            float sum = 0.f;
            #pragma unroll 8
            for (int j = 0; j < 64; j++) {
                const float p = __expf(prow[j] - mnew);
                prow[j] = p;
                sum += p;
            }
            l_i = l_i * f + sum;
            m_i = mnew;
            fac[tid] = f;
        }
        __syncthreads();

        // O = O*f + P @ V
        #pragma unroll
        for (int r = 0; r < 4; r++) {
            const float f = fac[ty*4 + r];
            #pragma unroll
            for (int c = 0; c < 4; c++) oacc[r][c] *= f;
        }
        #pragma unroll 4
        for (int j = 0; j < 64; j++) {
            const float4 v4 = *(float4*)(vs + j*64 + tx*4);
            #pragma unroll
            for (int r = 0; r < 4; r++) {
                const float p = ss[(ty*4+r)*64 + j];
                oacc[r][0] += p * v4.x;
                oacc[r][1] += p * v4.y;
                oacc[r][2] += p * v4.z;
                oacc[r][3] += p * v4.w;
            }
        }
        __syncthreads();
    }

    if (tid < 64) fac[tid] = 1.0f / l_i;
    __syncthreads();

    #pragma unroll
    for (int r = 0; r < 4; r++) {
        const int ig = i0 + ty*4 + r;
        const float li = fac[ty*4 + r];
        float4 o;
        o.x = oacc[r][0]*li; o.y = oacc[r][1]*li;
        o.z = oacc[r][2]*li; o.w = oacc[r][3]*li;
        *(float4*)(g_ao + ((size_t)b * N_ + ig) * 1024 + h*64 + tx*4) = o;
    }
}

// ---------------------------------------------------------------------------
// Output GEMM: d_out(4096 x 1024) = g_ao @ Wout. Same 128x128x8 tiling.
// ---------------------------------------------------------------------------
__global__ void gemm_out_kernel(const float* __restrict__ Wout,
                                float* __restrict__ out) {
    const int bm = blockIdx.y * 128;
    const int bn = blockIdx.x * 128;
    __shared__ float As[8][128];
    __shared__ float Bs[8][128];
    const float* __restrict__ A = g_ao;

    const int tid  = threadIdx.x;
    const int arow = tid >> 1, ak = (tid & 1) * 4;
    const int bkr  = tid >> 5, bcol = (tid & 31) * 4;
    const int ty   = tid >> 4, tx = tid & 15;

    float acc[8][8] = {};
    for (int k0 = 0; k0 < 1024; k0 += 8) {
        float4 a4 = *(const float4*)(A + (size_t)(bm + arow) * 1024 + k0 + ak);
        As[ak+0][arow] = a4.x; As[ak+1][arow] = a4.y;
        As[ak+2][arow] = a4.z; As[ak+3][arow] = a4.w;
        *(float4*)&Bs[bkr][bcol] = *(const float4*)(Wout + (size_t)(k0 + bkr) * 1024 + bn + bcol);
        __syncthreads();
        #pragma unroll
        for (int kk = 0; kk < 8; kk++) {
            float ar[8], br[8];
            *(float4*)(ar)   = *(float4*)&As[kk][ty*8];
            *(float4*)(ar+4) = *(float4*)&As[kk][ty*8+4];
            *(float4*)(br)   = *(float4*)&Bs[kk][tx*8];
            *(float4*)(br+4) = *(float4*)&Bs[kk][tx*8+4];
            #pragma unroll
            for (int i = 0; i < 8; i++)
                #pragma unroll
                for (int j = 0; j < 8; j++)
                    acc[i][j] += ar[i] * br[j];
        }
        __syncthreads();
    }
    #pragma unroll
    for (int i = 0; i < 8; i++) {
        const int row = bm + ty*8 + i;
        float* op = out + (size_t)row * 1024 + bn + tx*8;
        float4 o0, o1;
        o0.x = acc[i][0]; o0.y = acc[i][1]; o0.z = acc[i][2]; o0.w = acc[i][3];
        o1.x = acc[i][4]; o1.y = acc[i][5]; o1.z = acc[i][6]; o1.w = acc[i][7];
        *(float4*)(op)     = o0;
        *(float4*)(op + 4) = o1;
    }
}

// ---------------------------------------------------------------------------
extern "C" void kernel_launch(void* const* d_in, const int* in_sizes, int n_in,
                              void* d_out, int out_size) {
    const float* x         = (const float*)d_in[0];
    const float* attn_bias = (const float*)d_in[1];
    const void*  cmask     = (const void*) d_in[2];
    const float* gamma     = (const float*)d_in[3];
    const float* null_kv   = (const float*)d_in[4];
    const float* Wq        = (const float*)d_in[5];
    const float* Wkv       = (const float*)d_in[6];
    const float* q_scale   = (const float*)d_in[7];
    const float* k_scale   = (const float*)d_in[8];
    const float* Wout      = (const float*)d_in[9];
    float* out = (float*)d_out;

    static const size_t attn_smem = (4 * 4096 + 64) * sizeof(float);  // 65792 B
    cudaFuncSetAttribute(attn_kernel,
                         cudaFuncAttributeMaxDynamicSharedMemorySize,
                         (int)attn_smem);

    detect_mask_kernel<<<1, 256>>>((const unsigned char*)cmask);
    ln_kernel<<<ROWS_, 256>>>(x, gamma);
    gemm_qkv_kernel<<<dim3(24, 32), 256>>>(Wq, Wkv);
    {
        const int total_warps = BH_ * NK_;           // 65568
        const int blocks = (total_warps * 32 + 255) / 256;
        norm_kernel<<<blocks, 256>>>(null_kv, q_scale, k_scale);
    }
    attn_kernel<<<BH_ * 32, 256, attn_smem>>>(attn_bias, cmask);
    gemm_out_kernel<<<dim3(8, 32), 256>>>(Wout, out);
}

// round 3
// speedup vs baseline: 5.5825x; 5.5825x over previous
#include <cuda_runtime.h>
#include <math.h>
#include <float.h>

// Problem dims
#define B_   2
#define N_   2048
#define D_   1024
#define H_   16
#define DH_  64
#define C_   64
#define NK_  2049            // N+1 (null kv prepended)
#define BH_  (B_*H_)         // 32
#define ROWS_ (B_*N_)        // 4096
#define LDBIAS_ (C_+N_)      // 2112

// Scratch (device globals: allocation-free rule)
__device__ float g_xn[ROWS_*D_];        // layernormed x
__device__ float g_q [BH_*N_ *DH_];     // head-major q
__device__ float g_k [BH_*NK_*DH_];     // head-major k (row 0 = null)
__device__ float g_v [BH_*NK_*DH_];     // head-major v (row 0 = null)
__device__ float g_ao[ROWS_*D_];        // attention output (b,n,h*64+d)
__device__ int   g_mask_mode;           // 1 = 1-byte mask, 0 = 4-byte mask

// ---------------------------------------------------------------------------
// tf32 helpers
// ---------------------------------------------------------------------------
__device__ __forceinline__ unsigned f2tf(float f) {
    unsigned u;
    asm("cvt.rna.tf32.f32 %0, %1;" : "=r"(u) : "f"(f));
    return u;
}

__device__ __forceinline__ void mma8(float* c, const unsigned* a, const unsigned* b) {
    asm volatile(
        "mma.sync.aligned.m16n8k8.row.col.f32.tf32.tf32.f32 "
        "{%0,%1,%2,%3}, {%4,%5,%6,%7}, {%8,%9}, {%0,%1,%2,%3};"
        : "+f"(c[0]), "+f"(c[1]), "+f"(c[2]), "+f"(c[3])
        : "r"(a[0]), "r"(a[1]), "r"(a[2]), "r"(a[3]), "r"(b[0]), "r"(b[1]));
}

// ---------------------------------------------------------------------------
// Mask dtype detection (bool may be 1-byte or 4-byte serialized)
// ---------------------------------------------------------------------------
__global__ void detect_mask_kernel(const unsigned char* __restrict__ cm) {
    __shared__ int flag;
    if (threadIdx.x == 0) flag = 0;
    __syncthreads();
    int any = 0;
    for (int i = threadIdx.x; i < 1024; i += blockDim.x)
        if (cm[4*i + 1] != 0) any = 1;
    if (any) atomicOr(&flag, 1);
    __syncthreads();
    if (threadIdx.x == 0) g_mask_mode = flag;
}

// ---------------------------------------------------------------------------
// LayerNorm
// ---------------------------------------------------------------------------
__global__ void ln_kernel(const float* __restrict__ x,
                          const float* __restrict__ gamma) {
    const int row = blockIdx.x;
    const int tid = threadIdx.x;
    const float4 a = ((const float4*)(x + (size_t)row * D_))[tid];
    float s  = a.x + a.y + a.z + a.w;
    float s2 = a.x*a.x + a.y*a.y + a.z*a.z + a.w*a.w;
    #pragma unroll
    for (int o = 16; o > 0; o >>= 1) {
        s  += __shfl_xor_sync(0xFFFFFFFFu, s,  o);
        s2 += __shfl_xor_sync(0xFFFFFFFFu, s2, o);
    }
    __shared__ float rs[8], rs2[8];
    if ((tid & 31) == 0) { rs[tid >> 5] = s; rs2[tid >> 5] = s2; }
    __syncthreads();
    float S = 0.f, S2 = 0.f;
    #pragma unroll
    for (int i = 0; i < 8; i++) { S += rs[i]; S2 += rs2[i]; }
    const float mu  = S * (1.0f / D_);
    const float var = S2 * (1.0f / D_) - mu * mu;
    const float inv = rsqrtf(var + 1e-5f);
    const float4 g = ((const float4*)gamma)[tid];
    float4 o;
    o.x = (a.x - mu) * inv * g.x;
    o.y = (a.y - mu) * inv * g.y;
    o.z = (a.z - mu) * inv * g.z;
    o.w = (a.w - mu) * inv * g.w;
    ((float4*)(g_xn + (size_t)row * D_))[tid] = o;
}

// ---------------------------------------------------------------------------
// tf32 tensor-core GEMM core: 128x128 tile, BK=16, 256 threads (8 warps 4x2).
// ---------------------------------------------------------------------------
#define AS_STR 20
#define BS_STR2 136

struct GemmSmem {
    float As[2][128*AS_STR];
    float Bs[2][16*BS_STR2];
};

__device__ __forceinline__ void gemm_core_compute(
    const GemmSmem* sm, int buf, int wm, int wn, int gid, int tig,
    float acc[2][8][4])
{
    const unsigned* ab = (const unsigned*)sm->As[buf];
    const unsigned* bb = (const unsigned*)sm->Bs[buf];
    #pragma unroll
    for (int kk = 0; kk < 2; kk++) {
        unsigned afr[2][4];
        #pragma unroll
        for (int mt = 0; mt < 2; mt++) {
            const int r = wm*32 + mt*16 + gid;
            const int c = kk*8 + tig;
            afr[mt][0] = ab[(size_t)r*AS_STR + c];
            afr[mt][1] = ab[(size_t)(r+8)*AS_STR + c];
            afr[mt][2] = ab[(size_t)r*AS_STR + c + 4];
            afr[mt][3] = ab[(size_t)(r+8)*AS_STR + c + 4];
        }
        unsigned bfr[8][2];
        #pragma unroll
        for (int nt = 0; nt < 8; nt++) {
            const int k = kk*8 + tig;
            const int n = wn*64 + nt*8 + gid;
            bfr[nt][0] = bb[(size_t)k*BS_STR2 + n];
            bfr[nt][1] = bb[(size_t)(k+4)*BS_STR2 + n];
        }
        #pragma unroll
        for (int mt = 0; mt < 2; mt++)
            #pragma unroll
            for (int nt = 0; nt < 8; nt++)
                mma8(acc[mt][nt], afr[mt], bfr[nt]);
    }
}

__device__ __forceinline__ void gemm_main_loop(
    const float* __restrict__ A, const float* __restrict__ Bp,
    int ldb, int cb, int bm, GemmSmem* sm,
    int wm, int wn, int gid, int tig, float acc[2][8][4])
{
    const int tid = threadIdx.x;
    const int ar = tid >> 2, akc = (tid & 3) * 4;
    const int bk = tid >> 5, bnc = (tid & 31) * 4;

    float4 ra0, ra1, rb0, rb1;
    ra0 = *(const float4*)(A + (size_t)(bm + ar) * 1024 + akc);
    ra1 = *(const float4*)(A + (size_t)(bm + ar + 64) * 1024 + akc);
    rb0 = *(const float4*)(Bp + (size_t)bk * ldb + cb + bnc);
    rb1 = *(const float4*)(Bp + (size_t)(bk + 8) * ldb + cb + bnc);
    {
        unsigned* d0 = (unsigned*)&sm->As[0][ar*AS_STR + akc];
        d0[0]=f2tf(ra0.x); d0[1]=f2tf(ra0.y); d0[2]=f2tf(ra0.z); d0[3]=f2tf(ra0.w);
        unsigned* d1 = (unsigned*)&sm->As[0][(ar+64)*AS_STR + akc];
        d1[0]=f2tf(ra1.x); d1[1]=f2tf(ra1.y); d1[2]=f2tf(ra1.z); d1[3]=f2tf(ra1.w);
        unsigned* e0 = (unsigned*)&sm->Bs[0][bk*BS_STR2 + bnc];
        e0[0]=f2tf(rb0.x); e0[1]=f2tf(rb0.y); e0[2]=f2tf(rb0.z); e0[3]=f2tf(rb0.w);
        unsigned* e1 = (unsigned*)&sm->Bs[0][(bk+8)*BS_STR2 + bnc];
        e1[0]=f2tf(rb1.x); e1[1]=f2tf(rb1.y); e1[2]=f2tf(rb1.z); e1[3]=f2tf(rb1.w);
    }
    __syncthreads();

    int buf = 0;
    for (int kt = 0; kt < 64; kt++) {
        if (kt < 63) {
            const int k0 = (kt + 1) * 16;
            ra0 = *(const float4*)(A + (size_t)(bm + ar) * 1024 + k0 + akc);
            ra1 = *(const float4*)(A + (size_t)(bm + ar + 64) * 1024 + k0 + akc);
            rb0 = *(const float4*)(Bp + (size_t)(k0 + bk) * ldb + cb + bnc);
            rb1 = *(const float4*)(Bp + (size_t)(k0 + bk + 8) * ldb + cb + bnc);
        }
        gemm_core_compute(sm, buf, wm, wn, gid, tig, acc);
        if (kt < 63) {
            const int nb = buf ^ 1;
            unsigned* d0 = (unsigned*)&sm->As[nb][ar*AS_STR + akc];
            d0[0]=f2tf(ra0.x); d0[1]=f2tf(ra0.y); d0[2]=f2tf(ra0.z); d0[3]=f2tf(ra0.w);
            unsigned* d1 = (unsigned*)&sm->As[nb][(ar+64)*AS_STR + akc];
            d1[0]=f2tf(ra1.x); d1[1]=f2tf(ra1.y); d1[2]=f2tf(ra1.z); d1[3]=f2tf(ra1.w);
            unsigned* e0 = (unsigned*)&sm->Bs[nb][bk*BS_STR2 + bnc];
            e0[0]=f2tf(rb0.x); e0[1]=f2tf(rb0.y); e0[2]=f2tf(rb0.z); e0[3]=f2tf(rb0.w);
            unsigned* e1 = (unsigned*)&sm->Bs[nb][(bk+8)*BS_STR2 + bnc];
            e1[0]=f2tf(rb1.x); e1[1]=f2tf(rb1.y); e1[2]=f2tf(rb1.z); e1[3]=f2tf(rb1.w);
            __syncthreads();
            buf = nb;
        }
    }
}

// QKV GEMM: C(4096 x 3072) = xn @ [Wq | Wkv], scatter epilogue into q/k/v
__global__ __launch_bounds__(256)
void gemm_qkv_tc(const float* __restrict__ Wq, const float* __restrict__ Wkv) {
    __shared__ GemmSmem sm;
    const int tid = threadIdx.x;
    const int wid = tid >> 5, lane = tid & 31;
    const int gid = lane >> 2, tig = lane & 3;
    const int wm = wid & 3, wn = wid >> 2;
    const int bm = blockIdx.y * 128, bn = blockIdx.x * 128;
    const float* Bp; int ldb, cb;
    if (bn < 1024) { Bp = Wq;  ldb = 1024; cb = bn; }
    else           { Bp = Wkv; ldb = 2048; cb = bn - 1024; }

    float acc[2][8][4] = {};
    gemm_main_loop(g_xn, Bp, ldb, cb, bm, &sm, wm, wn, gid, tig, acc);

    #pragma unroll
    for (int mt = 0; mt < 2; mt++) {
        #pragma unroll
        for (int i = 0; i < 2; i++) {
            const int row = bm + wm*32 + mt*16 + gid + i*8;
            const int bidx = row >> 11, n = row & 2047;
            #pragma unroll
            for (int nt = 0; nt < 8; nt++) {
                const int col = bn + wn*64 + nt*8 + 2*tig;
                float2 v2 = make_float2(acc[mt][nt][i*2], acc[mt][nt][i*2+1]);
                if (col < 1024) {
                    const int hh = col >> 6, d = col & 63;
                    *(float2*)&g_q[(((size_t)(bidx*H_ + hh))*N_ + n)*DH_ + d] = v2;
                } else if (col < 2048) {
                    const int cc = col - 1024, hh = cc >> 6, d = cc & 63;
                    *(float2*)&g_k[(((size_t)(bidx*H_ + hh))*NK_ + n + 1)*DH_ + d] = v2;
                } else {
                    const int cc = col - 2048, hh = cc >> 6, d = cc & 63;
                    *(float2*)&g_v[(((size_t)(bidx*H_ + hh))*NK_ + n + 1)*DH_ + d] = v2;
                }
            }
        }
    }
}

// Output GEMM: d_out(4096 x 1024) = g_ao @ Wout
__global__ __launch_bounds__(256)
void gemm_out_tc(const float* __restrict__ Wout, float* __restrict__ out) {
    __shared__ GemmSmem sm;
    const int tid = threadIdx.x;
    const int wid = tid >> 5, lane = tid & 31;
    const int gid = lane >> 2, tig = lane & 3;
    const int wm = wid & 3, wn = wid >> 2;
    const int bm = blockIdx.y * 128, bn = blockIdx.x * 128;

    float acc[2][8][4] = {};
    gemm_main_loop(g_ao, Wout, 1024, bn, bm, &sm, wm, wn, gid, tig, acc);

    #pragma unroll
    for (int mt = 0; mt < 2; mt++) {
        #pragma unroll
        for (int i = 0; i < 2; i++) {
            const int row = bm + wm*32 + mt*16 + gid + i*8;
            #pragma unroll
            for (int nt = 0; nt < 8; nt++) {
                const int col = bn + wn*64 + nt*8 + 2*tig;
                *(float2*)&out[(size_t)row*1024 + col] =
                    make_float2(acc[mt][nt][i*2], acc[mt][nt][i*2+1]);
            }
        }
    }
}

// ---------------------------------------------------------------------------
// l2norm + scales + null kv fill
// ---------------------------------------------------------------------------
__global__ void norm_kernel(const float* __restrict__ null_kv,
                            const float* __restrict__ q_scale,
                            const float* __restrict__ k_scale) {
    const int gw   = (blockIdx.x * blockDim.x + threadIdx.x) >> 5;
    const int lane = threadIdx.x & 31;
    if (gw >= BH_ * NK_) return;
    const int bh = gw / NK_, j = gw - bh * NK_;
    const int h  = bh & 15;
    const int d0 = lane, d1 = lane + 32;
    const float ks0 = k_scale[d0], ks1 = k_scale[d1];

    if (j == 0) {
        const float k0 = null_kv[h*DH_ + d0], k1 = null_kv[h*DH_ + d1];
        const float v0 = null_kv[H_*DH_ + h*DH_ + d0];
        const float v1 = null_kv[H_*DH_ + h*DH_ + d1];
        float ss = k0*k0 + k1*k1;
        #pragma unroll
        for (int o = 16; o > 0; o >>= 1) ss += __shfl_xor_sync(0xFFFFFFFFu, ss, o);
        const float inv = 1.0f / fmaxf(sqrtf(ss), 1e-12f);
        float* kp = g_k + (size_t)bh * NK_ * DH_;
        float* vp = g_v + (size_t)bh * NK_ * DH_;
        kp[d0] = k0*inv*ks0; kp[d1] = k1*inv*ks1;
        vp[d0] = v0;         vp[d1] = v1;
    } else {
        float* kp = g_k + ((size_t)bh * NK_ + j) * DH_;
        float* qp = g_q + ((size_t)bh * N_ + (j-1)) * DH_;
        const float k0 = kp[d0], k1 = kp[d1];
        const float q0 = qp[d0], q1 = qp[d1];
        float ssk = k0*k0 + k1*k1;
        float ssq = q0*q0 + q1*q1;
        #pragma unroll
        for (int o = 16; o > 0; o >>= 1) {
            ssk += __shfl_xor_sync(0xFFFFFFFFu, ssk, o);
            ssq += __shfl_xor_sync(0xFFFFFFFFu, ssq, o);
        }
        const float invk = 1.0f / fmaxf(sqrtf(ssk), 1e-12f);
        const float invq = 1.0f / fmaxf(sqrtf(ssq), 1e-12f);
        const float qs0 = q_scale[d0], qs1 = q_scale[d1];
        kp[d0] = k0*invk*ks0; kp[d1] = k1*invk*ks1;
        qp[d0] = q0*invq*qs0; qp[d1] = q1*invq*qs1;
    }
}

// ---------------------------------------------------------------------------
// tf32 tensor-core flash attention.
// Block: 128 threads (4 warps), 64 q-rows (16 per warp), k/v tiles of 64.
// ---------------------------------------------------------------------------
#define KS_STR 68
#define VS_STR 72
#define BIA_STR 68
#define PS_STR 68

__global__ __launch_bounds__(128)
void attn_tc_kernel(const float* __restrict__ attn_bias,
                    const void*  __restrict__ cmask) {
    extern __shared__ float smf[];
    float* Ksf = smf;                      // 64*68 = 4352
    float* Vsf = smf + 4352;               // 64*72 = 4608
    float* Bia = smf + 8960;               // 64*68 = 4352
    float* Psf = smf + 13312;              // 4*16*68 = 4352
    int*   Mv  = (int*)(smf + 17664);      // 64
    unsigned* Ku = (unsigned*)Ksf;
    unsigned* Vu = (unsigned*)Vsf;
    unsigned* Pu = (unsigned*)Psf;

    const int tid = threadIdx.x;
    const int wid = tid >> 5, lane = tid & 31;
    const int gid = lane >> 2, tig = lane & 3;
    const int qt = blockIdx.x & 31, bh = blockIdx.x >> 5;
    const int b = bh >> 4, h = bh & 15;
    const int i0 = qt * 64;
    const int mode = g_mask_mode;
    const unsigned char* m8  = (const unsigned char*)cmask;
    const unsigned*      m32 = (const unsigned*)cmask;

    const int wr0 = wid*16 + gid;          // bias/local row for this thread's rows
    const int wr1 = wr0 + 8;

    // Q fragments: register-resident for the whole block
    unsigned qa[8][4];
    {
        const float* qb = g_q + ((size_t)bh*N_ + i0 + wid*16)*DH_;
        #pragma unroll
        for (int ks = 0; ks < 8; ks++) {
            qa[ks][0] = f2tf(qb[gid*64 + ks*8 + tig]);
            qa[ks][1] = f2tf(qb[(gid+8)*64 + ks*8 + tig]);
            qa[ks][2] = f2tf(qb[gid*64 + ks*8 + tig + 4]);
            qa[ks][3] = f2tf(qb[(gid+8)*64 + ks*8 + tig + 4]);
        }
    }

    float O[8][4];
    #pragma unroll
    for (int nt = 0; nt < 8; nt++)
        #pragma unroll
        for (int i = 0; i < 4; i++) O[nt][i] = 0.f;
    float m0 = -FLT_MAX, m1 = -FLT_MAX, l0 = 0.f, l1 = 0.f;

    const float* kb = g_k + (size_t)bh * NK_ * DH_;
    const float* vb = g_v + (size_t)bh * NK_ * DH_;
    unsigned* pw = Pu + wid * (16 * PS_STR);

    for (int t = 0; t < 33; t++) {
        const int jb = t * 64;
        const int navail = NK_ - jb;

        // ---- stage K, V (tf32), bias (fp32), mask ----
        #pragma unroll
        for (int i = 0; i < 8; i++) {
            const int idx = tid + i*128;
            const int r = idx >> 4, c4 = (idx & 15) * 4;
            float4 kk = make_float4(0.f,0.f,0.f,0.f), vv = kk;
            if (r < navail) {
                kk = *(const float4*)(kb + (size_t)(jb + r)*64 + c4);
                vv = *(const float4*)(vb + (size_t)(jb + r)*64 + c4);
            }
            unsigned* kd = Ku + r*KS_STR + c4;
            kd[0]=f2tf(kk.x); kd[1]=f2tf(kk.y); kd[2]=f2tf(kk.z); kd[3]=f2tf(kk.w);
            unsigned* vd = Vu + r*VS_STR + c4;
            vd[0]=f2tf(vv.x); vd[1]=f2tf(vv.y); vd[2]=f2tf(vv.z); vd[3]=f2tf(vv.w);
        }
        #pragma unroll
        for (int i = 0; i < 32; i++) {
            const int idx = tid + i*128;
            const int r = idx >> 6, c = idx & 63;
            const int jg = jb + c;
            float bv = 0.f;
            if (jg >= 1 && jg <= N_)
                bv = attn_bias[(size_t)(C_ + i0 + r)*LDBIAS_ + (C_ - 1) + jg];
            Bia[r*BIA_STR + c] = bv;
        }
        if (tid < 64) {
            const int jg = jb + tid;
            int val = 0;
            if (jg == 0) val = 1;
            else if (jg <= N_)
                val = mode ? (m8[b*N_ + jg - 1] != 0) : (m32[b*N_ + jg - 1] != 0u);
            Mv[tid] = val;
        }
        __syncthreads();

        // ---- S = Q K^T ----
        float sc[8][4];
        #pragma unroll
        for (int nt = 0; nt < 8; nt++)
            #pragma unroll
            for (int i = 0; i < 4; i++) sc[nt][i] = 0.f;
        #pragma unroll
        for (int ks = 0; ks < 8; ks++)
            #pragma unroll
            for (int nt = 0; nt < 8; nt++) {
                unsigned bb[2];
                bb[0] = Ku[(nt*8 + gid)*KS_STR + ks*8 + tig];
                bb[1] = Ku[(nt*8 + gid)*KS_STR + ks*8 + tig + 4];
                mma8(sc[nt], qa[ks], bb);
            }

        // ---- scale + bias + mask, online softmax in registers ----
        float mx0 = -FLT_MAX, mx1 = -FLT_MAX;
        #pragma unroll
        for (int nt = 0; nt < 8; nt++) {
            const int c0 = nt*8 + 2*tig, c1 = c0 + 1;
            const int v0 = Mv[c0], v1 = Mv[c1];
            const float b00 = Bia[wr0*BIA_STR + c0], b01 = Bia[wr0*BIA_STR + c1];
            const float b10 = Bia[wr1*BIA_STR + c0], b11 = Bia[wr1*BIA_STR + c1];
            sc[nt][0] = v0 ? sc[nt][0]*8.f + b00 : -FLT_MAX;
            sc[nt][1] = v1 ? sc[nt][1]*8.f + b01 : -FLT_MAX;
            sc[nt][2] = v0 ? sc[nt][2]*8.f + b10 : -FLT_MAX;
            sc[nt][3] = v1 ? sc[nt][3]*8.f + b11 : -FLT_MAX;
            mx0 = fmaxf(mx0, fmaxf(sc[nt][0], sc[nt][1]));
            mx1 = fmaxf(mx1, fmaxf(sc[nt][2], sc[nt][3]));
        }
        mx0 = fmaxf(mx0, __shfl_xor_sync(0xFFFFFFFFu, mx0, 1));
        mx0 = fmaxf(mx0, __shfl_xor_sync(0xFFFFFFFFu, mx0, 2));
        mx1 = fmaxf(mx1, __shfl_xor_sync(0xFFFFFFFFu, mx1, 1));
        mx1 = fmaxf(mx1, __shfl_xor_sync(0xFFFFFFFFu, mx1, 2));
        const float mn0 = fmaxf(m0, mx0), mn1 = fmaxf(m1, mx1);
        const float f0 = __expf(m0 - mn0), f1 = __expf(m1 - mn1);
        float s0 = 0.f, s1 = 0.f;
        #pragma unroll
        for (int nt = 0; nt < 8; nt++) {
            const float p0 = __expf(sc[nt][0] - mn0);
            const float p1 = __expf(sc[nt][1] - mn0);
            const float p2 = __expf(sc[nt][2] - mn1);
            const float p3 = __expf(sc[nt][3] - mn1);
            s0 += p0 + p1; s1 += p2 + p3;
            const int c0 = nt*8 + 2*tig;
            *(uint2*)(pw + gid*PS_STR + c0)     = make_uint2(f2tf(p0), f2tf(p1));
            *(uint2*)(pw + (gid+8)*PS_STR + c0) = make_uint2(f2tf(p2), f2tf(p3));
        }
        s0 += __shfl_xor_sync(0xFFFFFFFFu, s0, 1);
        s0 += __shfl_xor_sync(0xFFFFFFFFu, s0, 2);
        s1 += __shfl_xor_sync(0xFFFFFFFFu, s1, 1);
        s1 += __shfl_xor_sync(0xFFFFFFFFu, s1, 2);
        l0 = l0 * f0 + s0; l1 = l1 * f1 + s1;
        m0 = mn0; m1 = mn1;
        #pragma unroll
        for (int nt = 0; nt < 8; nt++) {
            O[nt][0] *= f0; O[nt][1] *= f0;
            O[nt][2] *= f1; O[nt][3] *= f1;
        }
        __syncwarp();

        // ---- O += P V ----
        #pragma unroll
        for (int ks = 0; ks < 8; ks++) {
            unsigned pa[4];
            pa[0] = pw[gid*PS_STR + ks*8 + tig];
            pa[1] = pw[(gid+8)*PS_STR + ks*8 + tig];
            pa[2] = pw[gid*PS_STR + ks*8 + tig + 4];
            pa[3] = pw[(gid+8)*PS_STR + ks*8 + tig + 4];
            #pragma unroll
            for (int nt = 0; nt < 8; nt++) {
                unsigned bb[2];
                bb[0] = Vu[(ks*8 + tig)*VS_STR + nt*8 + gid];
                bb[1] = Vu[(ks*8 + tig + 4)*VS_STR + nt*8 + gid];
                mma8(O[nt], pa, bb);
            }
        }
        __syncthreads();
    }

    const float inv0 = 1.f / l0, inv1 = 1.f / l1;
    float* ob = g_ao + ((size_t)b*N_ + i0 + wid*16)*1024 + h*64;
    #pragma unroll
    for (int nt = 0; nt < 8; nt++) {
        const int c0 = nt*8 + 2*tig;
        *(float2*)(ob + (size_t)gid*1024 + c0) =
            make_float2(O[nt][0]*inv0, O[nt][1]*inv0);
        *(float2*)(ob + (size_t)(gid+8)*1024 + c0) =
            make_float2(O[nt][2]*inv1, O[nt][3]*inv1);
    }
}

// ---------------------------------------------------------------------------
extern "C" void kernel_launch(void* const* d_in, const int* in_sizes, int n_in,
                              void* d_out, int out_size) {
    const float* x         = (const float*)d_in[0];
    const float* attn_bias = (const float*)d_in[1];
    const void*  cmask     = (const void*) d_in[2];
    const float* gamma     = (const float*)d_in[3];
    const float* null_kv   = (const float*)d_in[4];
    const float* Wq        = (const float*)d_in[5];
    const float* Wkv       = (const float*)d_in[6];
    const float* q_scale   = (const float*)d_in[7];
    const float* k_scale   = (const float*)d_in[8];
    const float* Wout      = (const float*)d_in[9];
    float* out = (float*)d_out;

    static const int attn_smem = 17728 * 4;  // 70912 B
    cudaFuncSetAttribute(attn_tc_kernel,
                         cudaFuncAttributeMaxDynamicSharedMemorySize,
                         attn_smem);

    detect_mask_kernel<<<1, 256>>>((const unsigned char*)cmask);
    ln_kernel<<<ROWS_, 256>>>(x, gamma);
    gemm_qkv_tc<<<dim3(24, 32), 256>>>(Wq, Wkv);
    {
        const int total_warps = BH_ * NK_;
        const int blocks = (total_warps * 32 + 255) / 256;
        norm_kernel<<<blocks, 256>>>(null_kv, q_scale, k_scale);
    }
    attn_tc_kernel<<<BH_ * 32, 128, attn_smem>>>(attn_bias, cmask);
    gemm_out_tc<<<dim3(8, 32), 256>>>(Wout, out);
}